// round 14
// baseline (speedup 1.0000x reference)
#include <cuda_runtime.h>
#include <cuda_fp16.h>
#include <math.h>
#include <stdint.h>

// ---------------- problem constants ----------------
#define HH 56
#define WW_ 56
#define CC 512
#define NHEAD 16
#define WSZ 7
#define SSH 3
#define HID 2048
#define HD 32
#define NTOK 49
#define NWH 8
#define NWW 8
#define NWIN 64
#define BB 16
#define TOT (BB*HH*WW_)   // 50176 tokens
#define LN_EPS 1e-5f
#define ATT_SCALE 0.17677669529663687f
#define DIV7(x) (((x) * 9363) >> 16)    // exact for 0..63

// ---------------- scratch (device globals, no allocs) ----------------
__device__ __align__(16) __half g_h16  [TOT * CC];
__device__ __align__(16) __half g_qkv16[TOT * 3 * CC];
__device__ __align__(16) __half g_o16  [TOT * CC];
__device__ __align__(16) __half g_act16[TOT * HID];
__device__ __align__(16) __half g_bias [NWIN * NHEAD * 64 * 64];   // 8 MB attn bias
#define WQKV_OFF 0
#define WPROJ_OFF (512*1536)
#define WFC1_OFF  (WPROJ_OFF + 512*512)
#define WFC2_OFF  (WFC1_OFF + 512*2048)
__device__ __align__(16) __half g_wt[512*1536 + 512*512 + 512*2048 + 2048*512];

// ---------------- common helpers ----------------
__device__ __forceinline__ void cp_async16(uint32_t dst, const void* src) {
    asm volatile("cp.async.cg.shared.global [%0], [%1], 16;" :: "r"(dst), "l"(src));
}
__device__ __forceinline__ void ldsm_x4(uint32_t& r0, uint32_t& r1,
                                        uint32_t& r2, uint32_t& r3, uint32_t addr) {
    asm volatile("ldmatrix.sync.aligned.m8n8.x4.shared.b16 {%0,%1,%2,%3}, [%4];"
                 : "=r"(r0), "=r"(r1), "=r"(r2), "=r"(r3) : "r"(addr));
}
__device__ __forceinline__ void ldsm_x4_t(uint32_t& r0, uint32_t& r1,
                                          uint32_t& r2, uint32_t& r3, uint32_t addr) {
    asm volatile("ldmatrix.sync.aligned.m8n8.x4.trans.shared.b16 {%0,%1,%2,%3}, [%4];"
                 : "=r"(r0), "=r"(r1), "=r"(r2), "=r"(r3) : "r"(addr));
}
__device__ __forceinline__ void mma16816(float* c, const uint32_t* a, const uint32_t* b) {
    asm volatile(
        "mma.sync.aligned.m16n8k16.row.col.f32.f16.f16.f32 "
        "{%0,%1,%2,%3}, {%4,%5,%6,%7}, {%8,%9}, {%0,%1,%2,%3};"
        : "+f"(c[0]), "+f"(c[1]), "+f"(c[2]), "+f"(c[3])
        : "r"(a[0]), "r"(a[1]), "r"(a[2]), "r"(a[3]), "r"(b[0]), "r"(b[1]));
}
__device__ __forceinline__ uint32_t packh2(float a, float b) {
    __half2 h = __floats2half2_rn(a, b);
    return *(uint32_t*)&h;
}
__device__ __forceinline__ float gelu_exact(float x) {
    return 0.5f * x * (1.0f + erff(x * 0.70710678118654752f));
}

// ---------------- attention bias precompute: [wloc][head][n][m] fp16 ----------------
__global__ void attnbias_kernel(const float* __restrict__ rpb, __half* __restrict__ bias)
{
    const int id = blockIdx.x;               // 1024 = 64 wloc * 16 head
    const int wloc = id >> 4, head = id & 15;
    const int wh = wloc >> 3, ww = wloc & 7;
    __half* bp = bias + ((size_t)id << 12);
    for (int i = threadIdx.x; i < 4096; i += 256) {
        int n = i >> 6, m = i & 63;
        float v;
        if (n >= NTOK || m >= NTOK) {
            v = -30000.0f;
        } else {
            int in = DIV7(n), jn = n - 7 * in;
            int im = DIV7(m), jm = m - 7 * im;
            int ridx = (jn - jm + 6) * 13 + (in - im + 6);
            int rn = wh * 7 + in, cn = ww * 7 + jn;
            int rm = wh * 7 + im, cm = ww * 7 + jm;
            int gn = ((rn < 49) ? 0 : ((rn < 53) ? 1 : 2)) * 3
                   + ((cn < 49) ? 0 : ((cn < 53) ? 1 : 2));
            int gm = ((rm < 49) ? 0 : ((rm < 53) ? 1 : 2)) * 3
                   + ((cm < 49) ? 0 : ((cm < 53) ? 1 : 2));
            v = rpb[ridx * NHEAD + head] + ((gn != gm) ? -100.0f : 0.0f);
        }
        bp[i] = __float2half(v);
    }
}

// ---------------- combined weight convert+transpose: 4 segments in one launch ----------------
__global__ void wconv_all_kernel(const float* __restrict__ W0, const float* __restrict__ W1,
                                 const float* __restrict__ W2, const float* __restrict__ W3,
                                 __half* __restrict__ wt)
{
    __shared__ float t[32][33];
    int b = blockIdx.x;
    const float* W; __half* Wt; int K, N, ntx, local;
    if (b < 768)       { W = W0; Wt = wt + WQKV_OFF;  K = 512;  N = 1536; ntx = 48; local = b; }
    else if (b < 1024) { W = W1; Wt = wt + WPROJ_OFF; K = 512;  N = 512;  ntx = 16; local = b - 768; }
    else if (b < 2048) { W = W2; Wt = wt + WFC1_OFF;  K = 512;  N = 2048; ntx = 64; local = b - 1024; }
    else               { W = W3; Wt = wt + WFC2_OFF;  K = 2048; N = 512;  ntx = 16; local = b - 2048; }
    int nx = (local % ntx) * 32, ky = (local / ntx) * 32;
    int tx = threadIdx.x, ty = threadIdx.y;      // 32 x 8
    #pragma unroll
    for (int j = 0; j < 32; j += 8)
        t[ty + j][tx] = W[(size_t)(ky + ty + j) * N + nx + tx];
    __syncthreads();
    #pragma unroll
    for (int j = 0; j < 32; j += 8)
        Wt[(size_t)(nx + ty + j) * K + ky + tx] = __float2half(t[tx][ty + j]);
}

// ---------------- LayerNorm, warp-per-row ----------------
template<bool GATHER>
__global__ __launch_bounds__(256)
void ln_kernel(const float* __restrict__ src,
               const float* __restrict__ scale,
               const float* __restrict__ bias,
               __half* __restrict__ dst)
{
    const int warp = threadIdx.x >> 5, lane = threadIdx.x & 31;
    const int t = blockIdx.x * 8 + warp;
    const float* sp;
    if (GATHER) {
        int b   = t / (NWIN * NTOK);
        int rem = t % (NWIN * NTOK);
        int win = rem / NTOK, pos = rem % NTOK;
        int wh = win / NWW, ww = win % NWW;
        int p = pos / WSZ, q = pos % WSZ;
        int row = (wh * WSZ + p + SSH) % HH;
        int col = (ww * WSZ + q + SSH) % WW_;
        sp = src + ((size_t)(b * HH + row) * WW_ + col) * CC;
    } else {
        sp = src + (size_t)t * CC;
    }
    __half* dp = dst + (size_t)t * CC;

    float4 v[4];
    float s = 0.f, s2 = 0.f;
    #pragma unroll
    for (int c = 0; c < 4; c++) {
        v[c] = *(const float4*)(sp + c * 128 + lane * 4);
        s  += v[c].x + v[c].y + v[c].z + v[c].w;
        s2 += v[c].x*v[c].x + v[c].y*v[c].y + v[c].z*v[c].z + v[c].w*v[c].w;
    }
    #pragma unroll
    for (int off = 16; off > 0; off >>= 1) {
        s  += __shfl_xor_sync(0xffffffffu, s,  off);
        s2 += __shfl_xor_sync(0xffffffffu, s2, off);
    }
    float mu = s * (1.0f / CC);
    float rs = rsqrtf(s2 * (1.0f / CC) - mu * mu + LN_EPS);

    #pragma unroll
    for (int c = 0; c < 4; c++) {
        int col = c * 128 + lane * 4;
        float4 sc = *(const float4*)(scale + col);
        float4 bi = *(const float4*)(bias  + col);
        float ox = (v[c].x - mu) * rs * sc.x + bi.x;
        float oy = (v[c].y - mu) * rs * sc.y + bi.y;
        float oz = (v[c].z - mu) * rs * sc.z + bi.z;
        float ow = (v[c].w - mu) * rs * sc.w + bi.w;
        uint2 o;
        o.x = packh2(ox, oy);
        o.y = packh2(oz, ow);
        *(uint2*)(dp + col) = o;
    }
}

// ---------------- fp16 tensor-core GEMM (unchanged winner) ----------------
#define HSTR 20
#define NSTG 4
#define STG_WORDS (128 * HSTR)
#define HG_SMEM (2 * NSTG * STG_WORDS * 4)   // 81920 bytes

template<int EPI, bool OUTH>
__global__ __launch_bounds__(256, 2)
void hgemm_kernel(const __half* __restrict__ A, const __half* __restrict__ Bt,
                  const float* __restrict__ bias, void* __restrict__ Cout,
                  const float* __restrict__ res, int M, int N, int K)
{
    extern __shared__ uint32_t sh[];
    uint32_t* As = sh;
    uint32_t* Bs = sh + NSTG * STG_WORDS;

    const int bx = blockIdx.x;
    const int by = blockIdx.y;
    const int tid = threadIdx.x;
    const int wid = tid >> 5, lane = tid & 31;
    const int wm = wid & 1;
    const int wn = wid >> 1;
    const int lr = lane >> 2;
    const int lc = lane & 3;
    const int sub  = lane >> 3;
    const int srow = lane & 7;

    float acc[4][4][4];
    #pragma unroll
    for (int i = 0; i < 4; i++)
        #pragma unroll
        for (int j = 0; j < 4; j++) {
            acc[i][j][0] = 0.f; acc[i][j][1] = 0.f;
            acc[i][j][2] = 0.f; acc[i][j][3] = 0.f;
        }

    const int srow_g = tid >> 1;
    const int sch    = tid & 1;
    const __half* Ag = A  + (size_t)(by * 128 + srow_g) * K + sch * 16;
    const __half* Bg = Bt + (size_t)(bx * 128 + srow_g) * K + sch * 16;
    const int NS = K >> 5;

    int a_row_off[4], b_row_off[2];
    #pragma unroll
    for (int mi = 0; mi < 4; mi++)
        a_row_off[mi] = (wm * 64 + mi * 16 + (sub & 1) * 8 + srow) * HSTR + (sub >> 1) * 4;
    #pragma unroll
    for (int p = 0; p < 2; p++)
        b_row_off[p] = (wn * 32 + p * 16 + (sub >> 1) * 8 + srow) * HSTR + (sub & 1) * 4;

    #pragma unroll
    for (int p = 0; p < NSTG - 1; p++) {
        uint32_t ad = (uint32_t)__cvta_generic_to_shared(
            As + p * STG_WORDS + srow_g * HSTR + sch * 8);
        uint32_t bd = (uint32_t)__cvta_generic_to_shared(
            Bs + p * STG_WORDS + srow_g * HSTR + sch * 8);
        const __half* Agp = Ag + p * 32;
        const __half* Bgp = Bg + p * 32;
        cp_async16(ad,      Agp);
        cp_async16(ad + 16, Agp + 8);
        cp_async16(bd,      Bgp);
        cp_async16(bd + 16, Bgp + 8);
        asm volatile("cp.async.commit_group;");
    }

    for (int s = 0; s < NS; s++) {
        asm volatile("cp.async.wait_group %0;" :: "n"(NSTG - 2));
        __syncthreads();

        if (s + NSTG - 1 < NS) {
            int p = s + NSTG - 1;
            int buf = p & (NSTG - 1);
            uint32_t ad = (uint32_t)__cvta_generic_to_shared(
                As + buf * STG_WORDS + srow_g * HSTR + sch * 8);
            uint32_t bd = (uint32_t)__cvta_generic_to_shared(
                Bs + buf * STG_WORDS + srow_g * HSTR + sch * 8);
            const __half* Agp = Ag + p * 32;
            const __half* Bgp = Bg + p * 32;
            cp_async16(ad,      Agp);
            cp_async16(ad + 16, Agp + 8);
            cp_async16(bd,      Bgp);
            cp_async16(bd + 16, Bgp + 8);
            asm volatile("cp.async.commit_group;");
        }

        const int buf = s & (NSTG - 1);
        const uint32_t abase = (uint32_t)__cvta_generic_to_shared(As + buf * STG_WORDS);
        const uint32_t bbase = (uint32_t)__cvta_generic_to_shared(Bs + buf * STG_WORDS);

        #pragma unroll
        for (int kk2 = 0; kk2 < 16; kk2 += 8) {
            uint32_t af[4][4], bf[4][2];
            #pragma unroll
            for (int mi = 0; mi < 4; mi++)
                ldsm_x4(af[mi][0], af[mi][1], af[mi][2], af[mi][3],
                        abase + (uint32_t)((a_row_off[mi] + kk2) << 2));
            #pragma unroll
            for (int p = 0; p < 2; p++)
                ldsm_x4(bf[2*p][0], bf[2*p][1], bf[2*p+1][0], bf[2*p+1][1],
                        bbase + (uint32_t)((b_row_off[p] + kk2) << 2));
            #pragma unroll
            for (int mi = 0; mi < 4; mi++)
                #pragma unroll
                for (int ni = 0; ni < 4; ni++)
                    mma16816(acc[mi][ni], af[mi], bf[ni]);
        }
    }

    const int m_base = by * 128 + wm * 64;
    const int n_base = bx * 128 + wn * 32;

    float2 bv[4];
    #pragma unroll
    for (int ni = 0; ni < 4; ni++)
        bv[ni] = *(const float2*)(bias + n_base + ni * 8 + 2 * lc);

    #pragma unroll
    for (int mi = 0; mi < 4; mi++) {
        int r0 = m_base + mi * 16 + lr;
        int r1 = r0 + 8;
        size_t orow0 = (size_t)r0, orow1 = (size_t)r1;
        if (EPI == 3) {
            int rows[2] = {r0, r1};
            size_t mapped[2];
            #pragma unroll
            for (int u = 0; u < 2; u++) {
                int t = rows[u];
                int b   = t / (NWIN * NTOK);
                int rem = t % (NWIN * NTOK);
                int win = rem / NTOK, pos = rem % NTOK;
                int wh = win >> 3, ww = win & 7;
                int p = pos / WSZ, q = pos % WSZ;
                int r = wh * WSZ + p + SSH; if (r >= HH) r -= HH;
                int c = ww * WSZ + q + SSH; if (c >= WW_) c -= WW_;
                mapped[u] = (size_t)(b * HH + r) * WW_ + c;
            }
            orow0 = mapped[0]; orow1 = mapped[1];
        }
        #pragma unroll
        for (int ni = 0; ni < 4; ni++) {
            int col = n_base + ni * 8 + 2 * lc;
            size_t off0 = orow0 * N + col;
            size_t off1 = orow1 * N + col;
            float2 v0, v1;
            v0.x = acc[mi][ni][0] + bv[ni].x;
            v0.y = acc[mi][ni][1] + bv[ni].y;
            v1.x = acc[mi][ni][2] + bv[ni].x;
            v1.y = acc[mi][ni][3] + bv[ni].y;
            if (EPI == 1) {
                v0.x = gelu_exact(v0.x); v0.y = gelu_exact(v0.y);
                v1.x = gelu_exact(v1.x); v1.y = gelu_exact(v1.y);
            }
            if (EPI == 2 || EPI == 3) {
                float2 q0 = *(const float2*)(res + off0);
                float2 q1 = *(const float2*)(res + off1);
                v0.x += q0.x; v0.y += q0.y;
                v1.x += q1.x; v1.y += q1.y;
            }
            if (OUTH) {
                __half* op = (__half*)Cout;
                *(__half2*)(op + off0) = __floats2half2_rn(v0.x, v0.y);
                *(__half2*)(op + off1) = __floats2half2_rn(v1.x, v1.y);
            } else {
                float* op = (float*)Cout;
                *(float2*)(op + off0) = v0;
                *(float2*)(op + off1) = v1;
            }
        }
    }
}

// ---------------- tensor-core windowed attention (precomputed bias) ----------------
#define ATT_TILE 2560
#define ATT_SMEM (8*3*ATT_TILE*2)   // 122880 bytes

__global__ __launch_bounds__(256, 1)
void attn_mma_kernel(const __half* __restrict__ qkv,
                     const __half* __restrict__ bias,
                     __half* __restrict__ o)
{
    extern __shared__ __half smha[];
    __half* tiles = smha;

    const int win = blockIdx.x;
    const int wloc = win & 63;
    const int tid = threadIdx.x;
    const int warp = tid >> 5, lane = tid & 31;
    const int lr = lane >> 2, lc = lane & 3;
    const int sub = lane >> 3, srow = lane & 7;

    __half* Qs = tiles + warp * 3 * ATT_TILE;
    __half* Ks = Qs + ATT_TILE;
    __half* Vs = Ks + ATT_TILE;
    const uint32_t qb = (uint32_t)__cvta_generic_to_shared(Qs);
    const uint32_t kb = (uint32_t)__cvta_generic_to_shared(Ks);
    const uint32_t vbb = (uint32_t)__cvta_generic_to_shared(Vs);

    // zero pad rows 49..63 of all three tiles (once)
    for (int i = lane; i < 225; i += 32) {
        int t = i / 75, rem = i % 75;
        int row = 49 + rem / 5, ch = rem % 5;
        *(uint4*)(Qs + t * ATT_TILE + row * 40 + ch * 8) = make_uint4(0, 0, 0, 0);
    }
    __syncwarp();

    for (int hh = 0; hh < 2; hh++) {
        const int head = warp * 2 + hh;
        const __half* base = qkv + (size_t)win * NTOK * (3 * CC) + head * HD;
        const __half* bias_h = bias + ((size_t)(wloc * NHEAD + head) << 12);
        for (int i = lane; i < 196; i += 32) {
            int row = i >> 2, ch = i & 3;
            const __half* rp = base + (size_t)row * (3 * CC) + ch * 8;
            *(uint4*)(Qs + row * 40 + ch * 8) = *(const uint4*)(rp);
            *(uint4*)(Ks + row * 40 + ch * 8) = *(const uint4*)(rp + CC);
            *(uint4*)(Vs + row * 40 + ch * 8) = *(const uint4*)(rp + 2 * CC);
        }
        __syncwarp();

        #pragma unroll
        for (int pass = 0; pass < 2; pass++) {
            const int rowb = pass * 32;

            // ---- S = Q @ K^T ----
            float sacc[2][8][4];
            #pragma unroll
            for (int mi = 0; mi < 2; mi++)
                #pragma unroll
                for (int ni = 0; ni < 8; ni++) {
                    sacc[mi][ni][0] = 0.f; sacc[mi][ni][1] = 0.f;
                    sacc[mi][ni][2] = 0.f; sacc[mi][ni][3] = 0.f;
                }
            #pragma unroll
            for (int kk = 0; kk < 2; kk++) {
                uint32_t qa[2][4], kf[8][2];
                #pragma unroll
                for (int mi = 0; mi < 2; mi++)
                    ldsm_x4(qa[mi][0], qa[mi][1], qa[mi][2], qa[mi][3],
                        qb + (uint32_t)((rowb + mi*16 + (sub&1)*8 + srow) * 80
                                        + ((sub>>1)*8 + kk*16) * 2));
                #pragma unroll
                for (int p = 0; p < 4; p++)
                    ldsm_x4(kf[2*p][0], kf[2*p][1], kf[2*p+1][0], kf[2*p+1][1],
                        kb + (uint32_t)((p*16 + (sub>>1)*8 + srow) * 80
                                        + ((sub&1)*8 + kk*16) * 2));
                #pragma unroll
                for (int mi = 0; mi < 2; mi++)
                    #pragma unroll
                    for (int ni = 0; ni < 8; ni++)
                        mma16816(sacc[mi][ni], qa[mi], kf[ni]);
            }

            // ---- bias (precomputed) + softmax in fragments ----
            float rinv[2][2];
            #pragma unroll
            for (int mi = 0; mi < 2; mi++) {
                int r0 = rowb + mi * 16 + lr;
                int r1 = r0 + 8;
                const __half* b0p = bias_h + (r0 << 6) + 2 * lc;
                const __half* b1p = bias_h + (r1 << 6) + 2 * lc;
                #pragma unroll
                for (int ni = 0; ni < 8; ni++) {
                    float2 f0 = __half22float2(*(const __half2*)(b0p + ni * 8));
                    float2 f1 = __half22float2(*(const __half2*)(b1p + ni * 8));
                    sacc[mi][ni][0] = sacc[mi][ni][0] * ATT_SCALE + f0.x;
                    sacc[mi][ni][1] = sacc[mi][ni][1] * ATT_SCALE + f0.y;
                    sacc[mi][ni][2] = sacc[mi][ni][2] * ATT_SCALE + f1.x;
                    sacc[mi][ni][3] = sacc[mi][ni][3] * ATT_SCALE + f1.y;
                }
                float mx0 = -1e30f, mx1 = -1e30f;
                #pragma unroll
                for (int ni = 0; ni < 8; ni++) {
                    mx0 = fmaxf(mx0, fmaxf(sacc[mi][ni][0], sacc[mi][ni][1]));
                    mx1 = fmaxf(mx1, fmaxf(sacc[mi][ni][2], sacc[mi][ni][3]));
                }
                mx0 = fmaxf(mx0, __shfl_xor_sync(0xffffffffu, mx0, 1));
                mx0 = fmaxf(mx0, __shfl_xor_sync(0xffffffffu, mx0, 2));
                mx1 = fmaxf(mx1, __shfl_xor_sync(0xffffffffu, mx1, 1));
                mx1 = fmaxf(mx1, __shfl_xor_sync(0xffffffffu, mx1, 2));
                float s0 = 0.f, s1 = 0.f;
                #pragma unroll
                for (int ni = 0; ni < 8; ni++) {
                    float e0 = __expf(sacc[mi][ni][0] - mx0);
                    float e1 = __expf(sacc[mi][ni][1] - mx0);
                    float e2 = __expf(sacc[mi][ni][2] - mx1);
                    float e3 = __expf(sacc[mi][ni][3] - mx1);
                    sacc[mi][ni][0] = e0; sacc[mi][ni][1] = e1;
                    sacc[mi][ni][2] = e2; sacc[mi][ni][3] = e3;
                    s0 += e0 + e1; s1 += e2 + e3;
                }
                s0 += __shfl_xor_sync(0xffffffffu, s0, 1);
                s0 += __shfl_xor_sync(0xffffffffu, s0, 2);
                s1 += __shfl_xor_sync(0xffffffffu, s1, 1);
                s1 += __shfl_xor_sync(0xffffffffu, s1, 2);
                rinv[mi][0] = 1.0f / s0;
                rinv[mi][1] = 1.0f / s1;
            }

            // ---- O = P @ V ----
            float oacc[2][4][4];
            #pragma unroll
            for (int mi = 0; mi < 2; mi++)
                #pragma unroll
                for (int ni = 0; ni < 4; ni++) {
                    oacc[mi][ni][0] = 0.f; oacc[mi][ni][1] = 0.f;
                    oacc[mi][ni][2] = 0.f; oacc[mi][ni][3] = 0.f;
                }
            #pragma unroll
            for (int kbk = 0; kbk < 4; kbk++) {
                uint32_t vf[4][2];
                #pragma unroll
                for (int g = 0; g < 2; g++)
                    ldsm_x4_t(vf[2*g][0], vf[2*g][1], vf[2*g+1][0], vf[2*g+1][1],
                        vbb + (uint32_t)((kbk*16 + (sub&1)*8 + srow) * 80
                                         + ((sub>>1)*8 + g*16) * 2));
                #pragma unroll
                for (int mi = 0; mi < 2; mi++) {
                    uint32_t ap[4];
                    ap[0] = packh2(sacc[mi][2*kbk][0],   sacc[mi][2*kbk][1]);
                    ap[1] = packh2(sacc[mi][2*kbk][2],   sacc[mi][2*kbk][3]);
                    ap[2] = packh2(sacc[mi][2*kbk+1][0], sacc[mi][2*kbk+1][1]);
                    ap[3] = packh2(sacc[mi][2*kbk+1][2], sacc[mi][2*kbk+1][3]);
                    #pragma unroll
                    for (int ni = 0; ni < 4; ni++)
                        mma16816(oacc[mi][ni], ap, vf[ni]);
                }
            }

            // ---- store rows < 49, normalized ----
            #pragma unroll
            for (int mi = 0; mi < 2; mi++) {
                int r0 = rowb + mi * 16 + lr;
                int r1 = r0 + 8;
                float i0 = rinv[mi][0], i1 = rinv[mi][1];
                #pragma unroll
                for (int ni = 0; ni < 4; ni++) {
                    int col = ni * 8 + 2 * lc;
                    if (r0 < NTOK)
                        *(__half2*)(o + (size_t)(win * NTOK + r0) * CC + head * HD + col)
                            = __floats2half2_rn(oacc[mi][ni][0] * i0, oacc[mi][ni][1] * i0);
                    if (r1 < NTOK)
                        *(__half2*)(o + (size_t)(win * NTOK + r1) * CC + head * HD + col)
                            = __floats2half2_rn(oacc[mi][ni][2] * i1, oacc[mi][ni][3] * i1);
                }
            }
        }
        __syncwarp();
    }
}

// ---------------- host launcher ----------------
extern "C" void kernel_launch(void* const* d_in, const int* in_sizes, int n_in,
                              void* d_out, int out_size)
{
    const float* x      = (const float*)d_in[0];
    const float* ln1_s  = (const float*)d_in[1];
    const float* ln1_b  = (const float*)d_in[2];
    const float* qkv_w  = (const float*)d_in[3];
    const float* qkv_b  = (const float*)d_in[4];
    const float* rpb    = (const float*)d_in[5];
    const float* proj_w = (const float*)d_in[6];
    const float* proj_b = (const float*)d_in[7];
    const float* ln2_s  = (const float*)d_in[8];
    const float* ln2_b  = (const float*)d_in[9];
    const float* fc1_w  = (const float*)d_in[10];
    const float* fc1_b  = (const float*)d_in[11];
    const float* fc2_w  = (const float*)d_in[12];
    const float* fc2_b  = (const float*)d_in[13];
    float* out = (float*)d_out;

    __half *ph, *pqkv, *po, *pact, *pwt, *pbias;
    cudaGetSymbolAddress((void**)&ph,    g_h16);
    cudaGetSymbolAddress((void**)&pqkv,  g_qkv16);
    cudaGetSymbolAddress((void**)&po,    g_o16);
    cudaGetSymbolAddress((void**)&pact,  g_act16);
    cudaGetSymbolAddress((void**)&pwt,   g_wt);
    cudaGetSymbolAddress((void**)&pbias, g_bias);

    static int smem_set = 0;
    if (!smem_set) {
        cudaFuncSetAttribute(hgemm_kernel<0, true >, cudaFuncAttributeMaxDynamicSharedMemorySize, HG_SMEM);
        cudaFuncSetAttribute(hgemm_kernel<1, true >, cudaFuncAttributeMaxDynamicSharedMemorySize, HG_SMEM);
        cudaFuncSetAttribute(hgemm_kernel<2, false>, cudaFuncAttributeMaxDynamicSharedMemorySize, HG_SMEM);
        cudaFuncSetAttribute(hgemm_kernel<3, false>, cudaFuncAttributeMaxDynamicSharedMemorySize, HG_SMEM);
        cudaFuncSetAttribute(attn_mma_kernel, cudaFuncAttributeMaxDynamicSharedMemorySize, ATT_SMEM);
        smem_set = 1;
    }

    // 0a. attention bias table (rpb + shift mask), 0b. weight convert+transpose
    attnbias_kernel<<<NWIN * NHEAD, 256>>>(rpb, pbias);
    wconv_all_kernel<<<3072, dim3(32, 8)>>>(qkv_w, proj_w, fc1_w, fc2_w, pwt);

    // 1. LN1 + shift + window partition -> fp16
    ln_kernel<true><<<TOT/8, 256>>>(x, ln1_s, ln1_b, ph);
    // 2. QKV GEMM
    hgemm_kernel<0, true><<<dim3(1536/128, TOT/128), 256, HG_SMEM>>>(
        ph, pwt + WQKV_OFF, qkv_b, pqkv, nullptr, TOT, 1536, 512);
    // 3. tensor-core windowed attention (precomputed bias)
    attn_mma_kernel<<<BB * NWIN, 256, ATT_SMEM>>>(pqkv, pbias, po);
    // 4. proj GEMM + fused window-reverse scatter + residual -> f32 out
    hgemm_kernel<3, false><<<dim3(512/128, TOT/128), 256, HG_SMEM>>>(
        po, pwt + WPROJ_OFF, proj_b, out, x, TOT, 512, 512);
    // 5. LN2 -> fp16
    ln_kernel<false><<<TOT/8, 256>>>(out, ln2_s, ln2_b, ph);
    // 6. FC1 + GELU
    hgemm_kernel<1, true><<<dim3(HID/128, TOT/128), 256, HG_SMEM>>>(
        ph, pwt + WFC1_OFF, fc1_b, pact, nullptr, TOT, HID, 512);
    // 7. FC2 + residual
    hgemm_kernel<2, false><<<dim3(512/128, TOT/128), 256, HG_SMEM>>>(
        pact, pwt + WFC2_OFF, fc2_b, out, out, TOT, 512, HID);
}